// round 15
// baseline (speedup 1.0000x reference)
#include <cuda_runtime.h>
#include <cuda_fp16.h>

#define B_ 2
#define HW_ 8192
#define D_ 512
#define L_ 4096
#define KN_ 32
#define HEADS_ 8
#define DH_ 64
#define INNER_ 512
#define MQ (B_ * HW_)   /* 16384 */
#define MC (B_ * L_)    /* 8192  */
#define GK 512          /* K of every GEMM */

// ---------------- device-global scratch (no cudaMalloc allowed) -------------
__device__ __half g_x16[MQ * D_];
__device__ __half g_c16[MC * D_];
__device__ __half g_wq16[D_ * INNER_];
__device__ __half g_wkv16[D_ * 2 * INNER_];
__device__ __half g_wo16[INNER_ * D_];
__device__ __half g_q16[MQ * INNER_];
__device__ __half g_kv16[MC * 2 * INNER_];
__device__ __half g_at16[MQ * INNER_];

// sync flags: [0]=kv_done(512), [1..128]=q_slab(4 each), [129..256]=at_slab(128 each)
__device__ int g_sync[257];

// ---------------- helpers ----------------------------------------------------
__device__ __forceinline__ void ldsm_x4(uint4 &r, unsigned addr) {
    asm volatile("ldmatrix.sync.aligned.m8n8.x4.shared.b16 {%0,%1,%2,%3}, [%4];"
        : "=r"(r.x), "=r"(r.y), "=r"(r.z), "=r"(r.w) : "r"(addr));
}
__device__ __forceinline__ void ldsm_x4_t(uint4 &r, unsigned addr) {
    asm volatile("ldmatrix.sync.aligned.m8n8.x4.trans.shared.b16 {%0,%1,%2,%3}, [%4];"
        : "=r"(r.x), "=r"(r.y), "=r"(r.z), "=r"(r.w) : "r"(addr));
}
__device__ __forceinline__ void mma_f16(float4 &d, const uint4 &a,
                                        unsigned b0, unsigned b1) {
    asm("mma.sync.aligned.m16n8k16.row.col.f32.f16.f16.f32 "
        "{%0,%1,%2,%3}, {%4,%5,%6,%7}, {%8,%9}, {%0,%1,%2,%3};"
        : "+f"(d.x), "+f"(d.y), "+f"(d.z), "+f"(d.w)
        : "r"(a.x), "r"(a.y), "r"(a.z), "r"(a.w), "r"(b0), "r"(b1));
}
__device__ __forceinline__ void cp16(unsigned saddr, const void* gaddr) {
    asm volatile("cp.async.cg.shared.global [%0], [%1], 16;"
        :: "r"(saddr), "l"(gaddr));
}
__device__ __forceinline__ void pdl_launch_dependents() {
    asm volatile("griddepcontrol.launch_dependents;" ::: "memory");
}
__device__ __forceinline__ void pdl_wait() {
    asm volatile("griddepcontrol.wait;" ::: "memory");
}
__device__ __forceinline__ void spin_until(volatile int* p, int target) {
    while (*p < target) __nanosleep(64);
}

// ---------------- reset sync flags ------------------------------------------
__global__ void reset_sync() {
    if (threadIdx.x < 257) g_sync[threadIdx.x] = 0;
}

// ---------------- merged fp32 -> fp16 convert (single launch) ---------------
#define CVT_C0 (MQ * D_ / 4)
#define CVT_C1 (CVT_C0 + MC * D_ / 4)
#define CVT_C2 (CVT_C1 + D_ * INNER_ / 4)
#define CVT_C3 (CVT_C2 + D_ * 2 * INNER_ / 4)
#define CVT_C4 (CVT_C3 + INNER_ * D_ / 4)
#define CVT_BLOCKS ((CVT_C4 / 2 + 255) / 256)

__global__ __launch_bounds__(256) void convert_all(
    const float4* __restrict__ x, const float4* __restrict__ c,
    const float4* __restrict__ wq, const float4* __restrict__ wkv,
    const float4* __restrict__ wo)
{
    pdl_launch_dependents();
    #pragma unroll
    for (int r = 0; r < 2; r++) {
        int i = (blockIdx.x * 2 + r) * 256 + threadIdx.x;
        if (i >= CVT_C4) return;
        const float4* s; uint2* d; int off;
        if      (i < CVT_C0) { s = x;   d = (uint2*)g_x16;   off = 0; }
        else if (i < CVT_C1) { s = c;   d = (uint2*)g_c16;   off = CVT_C0; }
        else if (i < CVT_C2) { s = wq;  d = (uint2*)g_wq16;  off = CVT_C1; }
        else if (i < CVT_C3) { s = wkv; d = (uint2*)g_wkv16; off = CVT_C2; }
        else                 { s = wo;  d = (uint2*)g_wo16;  off = CVT_C3; }
        const int j = i - off;
        float4 v = s[j];
        __half2 p0 = __floats2half2_rn(v.x, v.y);
        __half2 p1 = __floats2half2_rn(v.z, v.w);
        uint2 o;
        o.x = *(unsigned*)&p0;
        o.y = *(unsigned*)&p1;
        d[j] = o;
    }
}

// ---------------------------------------------------------------------------
// fp16 GEMM mainloop (verified R12/R13 layout). 128x128xK32, 8 warps, 2 CTA/SM,
// 5-stage cp.async.
// ---------------------------------------------------------------------------
#define AW 20
#define BW 68
#define B_OFF 10240
#define STG_BYTES 18944
#define NSTAGE 5
#define SMEM_BYTES (NSTAGE * STG_BYTES)

template <bool OUT_HALF>
__device__ __forceinline__ void gemm_tile(
    const __half* __restrict__ A, const __half* __restrict__ Bm,
    void* __restrict__ Cv, int ldb, int ldc,
    const float* __restrict__ bias, int blockCol, unsigned smbase)
{
    const int tid  = threadIdx.x;
    const int lane = tid & 31;
    const int warp = tid >> 5;
    const int wm   = (warp >> 1) * 32;
    const int wn   = (warp & 1) * 64;
    const int K = GK;

    const int ar = tid >> 2, ac = tid & 3;
    const int bk = tid >> 4, bc = tid & 15;
    const __half* gA = A + (size_t)ar * K + ac * 8;
    const __half* gB = Bm + (size_t)bk * ldb + blockCol + bc * 8;
    const unsigned a_sb = ar * 80 + ac * 16;
    const unsigned b_sb = bk * 272 + bc * 16;

    const int a_l_row = lane & 15;
    const int a_l_k   = (lane >> 4) << 2;
    const int b_l_k   = (lane & 7) + ((lane >> 4) << 3);
    const int b_l_n   = ((lane >> 3) & 1) << 2;

    float4 d[2][8];
    #pragma unroll
    for (int i = 0; i < 2; i++)
        #pragma unroll
        for (int j = 0; j < 8; j++) d[i][j] = make_float4(0.f, 0.f, 0.f, 0.f);

    auto issue = [&](int stage, int chunk) {
        unsigned s = smbase + stage * STG_BYTES;
        const int k0 = chunk * 32;
        cp16(s + a_sb,                  gA + k0);
        cp16(s + a_sb + 64 * 80,        gA + k0 + (size_t)64 * K);
        cp16(s + B_OFF + b_sb,          gB + (size_t)k0 * ldb);
        cp16(s + B_OFF + b_sb + 16 * 272, gB + (size_t)(k0 + 16) * ldb);
    };

    const int nK = K >> 5;
    #pragma unroll
    for (int c = 0; c < NSTAGE - 1; c++) {
        issue(c, c);
        asm volatile("cp.async.commit_group;" ::: "memory");
    }

    for (int i = 0; i < nK; i++) {
        const int stage = i % NSTAGE;
        asm volatile("cp.async.wait_group %0;" :: "n"(NSTAGE - 2) : "memory");
        __syncthreads();

        const unsigned sb = smbase + stage * STG_BYTES;
        #pragma unroll
        for (int kk = 0; kk < 2; kk++) {
            uint4 ah[2], bh[4];
            #pragma unroll
            for (int im = 0; im < 2; im++) {
                unsigned w = ((wm + im * 16 + a_l_row) * AW + kk * 8 + a_l_k) * 4;
                ldsm_x4(ah[im], sb + w);
            }
            #pragma unroll
            for (int ib = 0; ib < 4; ib++) {
                unsigned w = ((kk * 16 + b_l_k) * BW + ((wn + ib * 16) >> 1) + b_l_n) * 4;
                ldsm_x4_t(bh[ib], sb + B_OFF + w);
            }
            #pragma unroll
            for (int im = 0; im < 2; im++)
                #pragma unroll
                for (int ib = 0; ib < 4; ib++) {
                    mma_f16(d[im][ib * 2 + 0], ah[im], bh[ib].x, bh[ib].z);
                    mma_f16(d[im][ib * 2 + 1], ah[im], bh[ib].y, bh[ib].w);
                }
        }

        if (i + NSTAGE - 1 < nK) issue((i + NSTAGE - 1) % NSTAGE, i + NSTAGE - 1);
        asm volatile("cp.async.commit_group;" ::: "memory");
    }

    const int g  = lane >> 2;
    const int t2 = (lane & 3) << 1;
    #pragma unroll
    for (int im = 0; im < 2; im++) {
        const int row0 = wm + im * 16 + g;
        #pragma unroll
        for (int j = 0; j < 8; j++) {
            const int col = blockCol + wn + j * 8 + t2;
            float4 v = d[im][j];
            if (bias != nullptr) {
                float b0 = bias[col], b1 = bias[col + 1];
                v.x += b0; v.y += b1; v.z += b0; v.w += b1;
            }
            if (!OUT_HALF) {
                float* C = (float*)Cv;
                *(float2*)&C[(size_t)row0 * ldc + col]       = make_float2(v.x, v.y);
                *(float2*)&C[(size_t)(row0 + 8) * ldc + col] = make_float2(v.z, v.w);
            } else {
                __half* C = (__half*)Cv;
                *(__half2*)&C[(size_t)row0 * ldc + col]       = __floats2half2_rn(v.x, v.y);
                *(__half2*)&C[(size_t)(row0 + 8) * ldc + col] = __floats2half2_rn(v.z, v.w);
            }
        }
    }
}

// qkv projections; kv slabs FIRST (gy 0..127) so attention's kv dependency
// completes early, then q slabs (gy 128..255). Flags released per slab.
__global__ __launch_bounds__(256, 2) void qkv_gemm()
{
    extern __shared__ unsigned sm[];
    const unsigned smbase = (unsigned)__cvta_generic_to_shared(sm);
    pdl_launch_dependents();           // attn (flag-gated) may board SMs
    pdl_wait();                        // inputs from convert_all
    const int gy = blockIdx.y;
    const __half *A, *Bm; __half *C; int ldb, ldc;
    if (gy < 64) {                     // k slab
        A = g_c16 + (size_t)gy * 128 * GK;
        Bm = g_wkv16; ldb = 1024;
        C = g_kv16 + (size_t)gy * 128 * 1024; ldc = 1024;
    } else if (gy < 128) {             // v slab
        const int r = gy - 64;
        A = g_c16 + (size_t)r * 128 * GK;
        Bm = g_wkv16 + 512; ldb = 1024;
        C = g_kv16 + (size_t)r * 128 * 1024 + 512; ldc = 1024;
    } else {                           // q slab
        const int r = gy - 128;
        A = g_x16 + (size_t)r * 128 * GK;
        Bm = g_wq16; ldb = 512;
        C = g_q16 + (size_t)r * 128 * 512; ldc = 512;
    }
    gemm_tile<true>(A, Bm, C, ldb, ldc, nullptr, blockIdx.x * 128, smbase);

    __syncthreads();
    if (threadIdx.x == 0) {
        __threadfence();
        if (gy < 128) atomicAdd(&g_sync[0], 1);              // kv: -> 512
        else          atomicAdd(&g_sync[1 + (gy - 128)], 1); // q slab: -> 4
    }
}

__global__ __launch_bounds__(256, 2) void out_gemm(
    float* __restrict__ out, const float* __restrict__ bias)
{
    extern __shared__ unsigned sm[];
    const unsigned smbase = (unsigned)__cvta_generic_to_shared(sm);
    const int gy = blockIdx.y;
    if (threadIdx.x == 0) {
        spin_until((volatile int*)&g_sync[129 + gy], 128);   // slab's attn done
        __threadfence();
    }
    __syncthreads();
    const __half* A = g_at16 + (size_t)gy * 128 * GK;
    float* C = out + (size_t)gy * 128 * 512;
    gemm_tile<false>(A, g_wo16, C, 512, 512, bias, blockIdx.x * 128, smbase);
}

// ---------------------------------------------------------------------------
// Sparse neighbor attention (verified R11/R12 math). Flag-gated start per
// slab: needs all kv + its own q slab. Releases at-slab flag at end.
// ---------------------------------------------------------------------------
__global__ __launch_bounds__(256) void attn_kernel(
    const int* __restrict__ idx, const float* __restrict__ bias)
{
    const int bq   = blockIdx.x;
    const int b    = bq >> 13;
    const int h    = threadIdx.x >> 5;
    const int lane = threadIdx.x & 31;

    __shared__ float qs[INNER_];
    __shared__ int   rows_s[KN_];
    __shared__ float ps[HEADS_][KN_];

    pdl_launch_dependents();           // out (flag-gated) may board SMs

    // independent prologue: indices (input tensor)
    if (threadIdx.x < KN_)
        rows_s[threadIdx.x] =
            b * L_ + (idx[(size_t)bq * KN_ + threadIdx.x] & (L_ - 1));

    if (threadIdx.x == 0) {
        spin_until((volatile int*)&g_sync[0], 512);              // all kv
        spin_until((volatile int*)&g_sync[1 + (bq >> 7)], 4);    // my q slab
        __threadfence();
    }
    __syncthreads();

    const __half2* qsrc = (const __half2*)(g_q16 + (size_t)bq * INNER_);
    #pragma unroll
    for (int i = threadIdx.x; i < INNER_ / 2; i += 256) {
        float2 f = __half22float2(qsrc[i]);
        qs[i * 2] = f.x; qs[i * 2 + 1] = f.y;
    }
    __syncthreads();

    const int g  = lane >> 2;
    const int qd = lane & 3;
    float pv[4];
    #pragma unroll
    for (int p = 0; p < 4; p++) {
        const int rj = rows_s[p * 8 + g];
        const uint4* kp = (const uint4*)(g_kv16
            + (size_t)rj * (2 * INNER_) + h * DH_ + qd * 16);
        uint4 u0 = kp[0], u1 = kp[1];
        const float* q16p = qs + h * DH_ + qd * 16;
        float t = 0.f;
        {
            float2 f;
            f = __half22float2(*(__half2*)&u0.x); t = fmaf(q16p[0], f.x, t); t = fmaf(q16p[1], f.y, t);
            f = __half22float2(*(__half2*)&u0.y); t = fmaf(q16p[2], f.x, t); t = fmaf(q16p[3], f.y, t);
            f = __half22float2(*(__half2*)&u0.z); t = fmaf(q16p[4], f.x, t); t = fmaf(q16p[5], f.y, t);
            f = __half22float2(*(__half2*)&u0.w); t = fmaf(q16p[6], f.x, t); t = fmaf(q16p[7], f.y, t);
            f = __half22float2(*(__half2*)&u1.x); t = fmaf(q16p[8], f.x, t); t = fmaf(q16p[9], f.y, t);
            f = __half22float2(*(__half2*)&u1.y); t = fmaf(q16p[10], f.x, t); t = fmaf(q16p[11], f.y, t);
            f = __half22float2(*(__half2*)&u1.z); t = fmaf(q16p[12], f.x, t); t = fmaf(q16p[13], f.y, t);
            f = __half22float2(*(__half2*)&u1.w); t = fmaf(q16p[14], f.x, t); t = fmaf(q16p[15], f.y, t);
        }
        t += __shfl_xor_sync(0xffffffffu, t, 1);
        t += __shfl_xor_sync(0xffffffffu, t, 2);
        pv[p] = t;
    }
    const int src = (lane & 7) << 2;
    const float t0 = __shfl_sync(0xffffffffu, pv[0], src);
    const float t1 = __shfl_sync(0xffffffffu, pv[1], src);
    const float t2 = __shfl_sync(0xffffffffu, pv[2], src);
    const float t3 = __shfl_sync(0xffffffffu, pv[3], src);
    const int pselect = lane >> 3;
    float dot = (pselect == 0) ? t0 : (pselect == 1) ? t1 : (pselect == 2) ? t2 : t3;

    const float bj  = bias[(size_t)bq * KN_ + lane];
    float sim = dot * 0.125f + bj;

    float m = sim;
    #pragma unroll
    for (int o = 16; o; o >>= 1) m = fmaxf(m, __shfl_xor_sync(0xffffffffu, m, o));
    float e = __expf(sim - m);
    float s = e;
    #pragma unroll
    for (int o = 16; o; o >>= 1) s += __shfl_xor_sync(0xffffffffu, s, o);
    const float p = e / s;

    ps[h][lane] = p;
    __syncthreads();

    float2 acc = make_float2(0.f, 0.f);
    const int off = INNER_ + h * DH_ + lane * 2;
    #pragma unroll
    for (int jb = 0; jb < KN_; jb += 8) {
        float2 v2[8];
        #pragma unroll
        for (int u = 0; u < 8; u++) {
            const int rj = rows_s[jb + u];
            v2[u] = __half22float2(
                *(const __half2*)(g_kv16 + (size_t)rj * (2 * INNER_) + off));
        }
        #pragma unroll
        for (int u = 0; u < 8; u++) {
            const float pj = ps[h][jb + u];
            acc.x = fmaf(pj, v2[u].x, acc.x);
            acc.y = fmaf(pj, v2[u].y, acc.y);
        }
    }
    *(__half2*)(g_at16 + (size_t)bq * INNER_ + h * DH_ + lane * 2) =
        __floats2half2_rn(acc.x, acc.y);

    __syncthreads();
    if (threadIdx.x == 0) {
        __threadfence();
        atomicAdd(&g_sync[129 + (bq >> 7)], 1);              // -> 128 per slab
    }
}

// ---------------------------------------------------------------------------
extern "C" void kernel_launch(void* const* d_in, const int* in_sizes, int n_in,
                              void* d_out, int out_size)
{
    const float* x       = (const float*)d_in[0];
    const float* context = (const float*)d_in[1];
    const int*   idx     = (const int*)d_in[2];
    const float* bias    = (const float*)d_in[3];
    const float* Wq      = (const float*)d_in[4];
    const float* Wkv     = (const float*)d_in[5];
    const float* Wo      = (const float*)d_in[6];
    const float* bo      = (const float*)d_in[7];
    float*       out     = (float*)d_out;

    cudaFuncSetAttribute(qkv_gemm,
        cudaFuncAttributeMaxDynamicSharedMemorySize, SMEM_BYTES);
    cudaFuncSetAttribute(out_gemm,
        cudaFuncAttributeMaxDynamicSharedMemorySize, SMEM_BYTES);

    reset_sync<<<1, 288>>>();

    convert_all<<<CVT_BLOCKS, 256>>>(
        (const float4*)x, (const float4*)context,
        (const float4*)Wq, (const float4*)Wkv, (const float4*)Wo);

    cudaLaunchAttribute pdlAttr[1];
    pdlAttr[0].id = cudaLaunchAttributeProgrammaticStreamSerialization;
    pdlAttr[0].val.programmaticStreamSerializationAllowed = 1;

    {   // qkv (PDL: overlaps convert tail; pdl_wait gates on convert data)
        cudaLaunchConfig_t cfg = {};
        cfg.gridDim = dim3(4, 256);
        cfg.blockDim = dim3(256);
        cfg.dynamicSmemBytes = SMEM_BYTES;
        cfg.attrs = pdlAttr; cfg.numAttrs = 1;
        cudaLaunchKernelEx(&cfg, qkv_gemm);
    }
    {   // attn (PDL: boards during qkv; flag-gated per slab)
        cudaLaunchConfig_t cfg = {};
        cfg.gridDim = dim3(MQ);
        cfg.blockDim = dim3(256);
        cfg.attrs = pdlAttr; cfg.numAttrs = 1;
        cudaLaunchKernelEx(&cfg, attn_kernel, idx, bias);
    }
    {   // out (PDL: boards during attn; flag-gated per slab)
        cudaLaunchConfig_t cfg = {};
        cfg.gridDim = dim3(4, MQ / 128);
        cfg.blockDim = dim3(256);
        cfg.dynamicSmemBytes = SMEM_BYTES;
        cfg.attrs = pdlAttr; cfg.numAttrs = 1;
        cudaLaunchKernelEx(&cfg, out_gemm, out, bo);
    }
}

// round 16
// speedup vs baseline: 1.1381x; 1.1381x over previous
#include <cuda_runtime.h>
#include <cuda_fp16.h>

#define B_ 2
#define HW_ 8192
#define D_ 512
#define L_ 4096
#define KN_ 32
#define HEADS_ 8
#define DH_ 64
#define INNER_ 512
#define MQ (B_ * HW_)   /* 16384 */
#define MC (B_ * L_)    /* 8192  */
#define GK 512          /* K of every GEMM */

// ---------------- device-global scratch (no cudaMalloc allowed) -------------
__device__ __half g_x16[MQ * D_];
__device__ __half g_c16[MC * D_];
__device__ __half g_wq16[D_ * INNER_];
__device__ __half g_wkv16[D_ * 2 * INNER_];
__device__ __half g_wo16[INNER_ * D_];
__device__ __half g_q16[MQ * INNER_];
__device__ __half g_kv16[MC * 2 * INNER_];
__device__ __half g_at16[MQ * INNER_];

// ---------------- helpers ----------------------------------------------------
__device__ __forceinline__ void ldsm_x4(uint4 &r, unsigned addr) {
    asm volatile("ldmatrix.sync.aligned.m8n8.x4.shared.b16 {%0,%1,%2,%3}, [%4];"
        : "=r"(r.x), "=r"(r.y), "=r"(r.z), "=r"(r.w) : "r"(addr));
}
__device__ __forceinline__ void ldsm_x4_t(uint4 &r, unsigned addr) {
    asm volatile("ldmatrix.sync.aligned.m8n8.x4.trans.shared.b16 {%0,%1,%2,%3}, [%4];"
        : "=r"(r.x), "=r"(r.y), "=r"(r.z), "=r"(r.w) : "r"(addr));
}
__device__ __forceinline__ void mma_f16(float4 &d, const uint4 &a,
                                        unsigned b0, unsigned b1) {
    asm("mma.sync.aligned.m16n8k16.row.col.f32.f16.f16.f32 "
        "{%0,%1,%2,%3}, {%4,%5,%6,%7}, {%8,%9}, {%0,%1,%2,%3};"
        : "+f"(d.x), "+f"(d.y), "+f"(d.z), "+f"(d.w)
        : "r"(a.x), "r"(a.y), "r"(a.z), "r"(a.w), "r"(b0), "r"(b1));
}
__device__ __forceinline__ void cp16(unsigned saddr, const void* gaddr) {
    asm volatile("cp.async.cg.shared.global [%0], [%1], 16;"
        :: "r"(saddr), "l"(gaddr));
}

// ---------------- merged fp32 -> fp16 convert (single launch) ---------------
#define CVT_C0 (MQ * D_ / 4)
#define CVT_C1 (CVT_C0 + MC * D_ / 4)
#define CVT_C2 (CVT_C1 + D_ * INNER_ / 4)
#define CVT_C3 (CVT_C2 + D_ * 2 * INNER_ / 4)
#define CVT_C4 (CVT_C3 + INNER_ * D_ / 4)
#define CVT_BLOCKS ((CVT_C4 / 2 + 255) / 256)

__global__ __launch_bounds__(256) void convert_all(
    const float4* __restrict__ x, const float4* __restrict__ c,
    const float4* __restrict__ wq, const float4* __restrict__ wkv,
    const float4* __restrict__ wo)
{
    #pragma unroll
    for (int r = 0; r < 2; r++) {
        int i = (blockIdx.x * 2 + r) * 256 + threadIdx.x;
        if (i >= CVT_C4) return;
        const float4* s; uint2* d; int off;
        if      (i < CVT_C0) { s = x;   d = (uint2*)g_x16;   off = 0; }
        else if (i < CVT_C1) { s = c;   d = (uint2*)g_c16;   off = CVT_C0; }
        else if (i < CVT_C2) { s = wq;  d = (uint2*)g_wq16;  off = CVT_C1; }
        else if (i < CVT_C3) { s = wkv; d = (uint2*)g_wkv16; off = CVT_C2; }
        else                 { s = wo;  d = (uint2*)g_wo16;  off = CVT_C3; }
        const int j = i - off;
        float4 v = s[j];
        __half2 p0 = __floats2half2_rn(v.x, v.y);
        __half2 p1 = __floats2half2_rn(v.z, v.w);
        uint2 o;
        o.x = *(unsigned*)&p0;
        o.y = *(unsigned*)&p1;
        d[j] = o;
    }
}

// ---------------------------------------------------------------------------
// fp16 GEMM mainloop (verified R12/R13 layout). 128x128xK32, 8 warps, 2 CTA/SM,
// 5-stage cp.async.
// ---------------------------------------------------------------------------
#define AW 20
#define BW 68
#define B_OFF 10240
#define STG_BYTES 18944
#define NSTAGE 5
#define SMEM_BYTES (NSTAGE * STG_BYTES)

template <bool OUT_HALF>
__device__ __forceinline__ void gemm_tile(
    const __half* __restrict__ A, const __half* __restrict__ Bm,
    void* __restrict__ Cv, int ldb, int ldc,
    const float* __restrict__ bias, int blockCol, unsigned smbase)
{
    const int tid  = threadIdx.x;
    const int lane = tid & 31;
    const int warp = tid >> 5;
    const int wm   = (warp >> 1) * 32;
    const int wn   = (warp & 1) * 64;
    const int K = GK;

    const int ar = tid >> 2, ac = tid & 3;
    const int bk = tid >> 4, bc = tid & 15;
    const __half* gA = A + (size_t)ar * K + ac * 8;
    const __half* gB = Bm + (size_t)bk * ldb + blockCol + bc * 8;
    const unsigned a_sb = ar * 80 + ac * 16;
    const unsigned b_sb = bk * 272 + bc * 16;

    const int a_l_row = lane & 15;
    const int a_l_k   = (lane >> 4) << 2;
    const int b_l_k   = (lane & 7) + ((lane >> 4) << 3);
    const int b_l_n   = ((lane >> 3) & 1) << 2;

    float4 d[2][8];
    #pragma unroll
    for (int i = 0; i < 2; i++)
        #pragma unroll
        for (int j = 0; j < 8; j++) d[i][j] = make_float4(0.f, 0.f, 0.f, 0.f);

    auto issue = [&](int stage, int chunk) {
        unsigned s = smbase + stage * STG_BYTES;
        const int k0 = chunk * 32;
        cp16(s + a_sb,                  gA + k0);
        cp16(s + a_sb + 64 * 80,        gA + k0 + (size_t)64 * K);
        cp16(s + B_OFF + b_sb,          gB + (size_t)k0 * ldb);
        cp16(s + B_OFF + b_sb + 16 * 272, gB + (size_t)(k0 + 16) * ldb);
    };

    const int nK = K >> 5;
    #pragma unroll
    for (int c = 0; c < NSTAGE - 1; c++) {
        issue(c, c);
        asm volatile("cp.async.commit_group;" ::: "memory");
    }

    for (int i = 0; i < nK; i++) {
        const int stage = i % NSTAGE;
        asm volatile("cp.async.wait_group %0;" :: "n"(NSTAGE - 2) : "memory");
        __syncthreads();

        const unsigned sb = smbase + stage * STG_BYTES;
        #pragma unroll
        for (int kk = 0; kk < 2; kk++) {
            uint4 ah[2], bh[4];
            #pragma unroll
            for (int im = 0; im < 2; im++) {
                unsigned w = ((wm + im * 16 + a_l_row) * AW + kk * 8 + a_l_k) * 4;
                ldsm_x4(ah[im], sb + w);
            }
            #pragma unroll
            for (int ib = 0; ib < 4; ib++) {
                unsigned w = ((kk * 16 + b_l_k) * BW + ((wn + ib * 16) >> 1) + b_l_n) * 4;
                ldsm_x4_t(bh[ib], sb + B_OFF + w);
            }
            #pragma unroll
            for (int im = 0; im < 2; im++)
                #pragma unroll
                for (int ib = 0; ib < 4; ib++) {
                    mma_f16(d[im][ib * 2 + 0], ah[im], bh[ib].x, bh[ib].z);
                    mma_f16(d[im][ib * 2 + 1], ah[im], bh[ib].y, bh[ib].w);
                }
        }

        if (i + NSTAGE - 1 < nK) issue((i + NSTAGE - 1) % NSTAGE, i + NSTAGE - 1);
        asm volatile("cp.async.commit_group;" ::: "memory");
    }

    const int g  = lane >> 2;
    const int t2 = (lane & 3) << 1;
    #pragma unroll
    for (int im = 0; im < 2; im++) {
        const int row0 = wm + im * 16 + g;
        #pragma unroll
        for (int j = 0; j < 8; j++) {
            const int col = blockCol + wn + j * 8 + t2;
            float4 v = d[im][j];
            if (bias != nullptr) {
                float b0 = bias[col], b1 = bias[col + 1];
                v.x += b0; v.y += b1; v.z += b0; v.w += b1;
            }
            if (!OUT_HALF) {
                float* C = (float*)Cv;
                *(float2*)&C[(size_t)row0 * ldc + col]       = make_float2(v.x, v.y);
                *(float2*)&C[(size_t)(row0 + 8) * ldc + col] = make_float2(v.z, v.w);
            } else {
                __half* C = (__half*)Cv;
                *(__half2*)&C[(size_t)row0 * ldc + col]       = __floats2half2_rn(v.x, v.y);
                *(__half2*)&C[(size_t)(row0 + 8) * ldc + col] = __floats2half2_rn(v.z, v.w);
            }
        }
    }
}

__global__ __launch_bounds__(256, 2) void qkv_gemm()
{
    extern __shared__ unsigned sm[];
    const unsigned smbase = (unsigned)__cvta_generic_to_shared(sm);
    const int gy = blockIdx.y;
    const __half *A, *Bm; __half *C; int ldb, ldc;
    if (gy < 128) {
        A = g_x16 + (size_t)gy * 128 * GK;
        Bm = g_wq16; ldb = 512;
        C = g_q16 + (size_t)gy * 128 * 512; ldc = 512;
    } else if (gy < 192) {
        const int r = gy - 128;
        A = g_c16 + (size_t)r * 128 * GK;
        Bm = g_wkv16; ldb = 1024;
        C = g_kv16 + (size_t)r * 128 * 1024; ldc = 1024;
    } else {
        const int r = gy - 192;
        A = g_c16 + (size_t)r * 128 * GK;
        Bm = g_wkv16 + 512; ldb = 1024;
        C = g_kv16 + (size_t)r * 128 * 1024 + 512; ldc = 1024;
    }
    gemm_tile<true>(A, Bm, C, ldb, ldc, nullptr, blockIdx.x * 128, smbase);
}

__global__ __launch_bounds__(256, 2) void out_gemm(
    float* __restrict__ out, const float* __restrict__ bias)
{
    extern __shared__ unsigned sm[];
    const unsigned smbase = (unsigned)__cvta_generic_to_shared(sm);
    const __half* A = g_at16 + (size_t)blockIdx.y * 128 * GK;
    float* C = out + (size_t)blockIdx.y * 128 * 512;
    gemm_tile<false>(A, g_wo16, C, 512, 512, bias, blockIdx.x * 128, smbase);
}

// ---------------------------------------------------------------------------
// Sparse neighbor attention.
// K phase: 8 lanes cooperate per neighbor row (lane = group g2 x eighth e);
// pass p handles neighbor j = 4p + g2; each lane loads 16B at offset e*16 of
// the 128B head slice -> ONE LDG.128 per pass touches 4 lines (the minimum:
// each row's line exactly once). 8 passes x 4 = 32 wavefronts/warp vs 64.
// 3-deep butterfly per pass; 8 shuffles redistribute sim_j to lane j.
// V phase: staged rows/probs, batched coalesced loads (verified R10-R12).
// ---------------------------------------------------------------------------
__global__ __launch_bounds__(256) void attn_kernel(
    const int* __restrict__ idx, const float* __restrict__ bias)
{
    const int bq   = blockIdx.x;
    const int b    = bq >> 13;
    const int h    = threadIdx.x >> 5;
    const int lane = threadIdx.x & 31;

    __shared__ float qs[INNER_];
    __shared__ int   rows_s[KN_];
    __shared__ float ps[HEADS_][KN_];

    if (threadIdx.x < KN_)
        rows_s[threadIdx.x] =
            b * L_ + (idx[(size_t)bq * KN_ + threadIdx.x] & (L_ - 1));
    const __half2* qsrc = (const __half2*)(g_q16 + (size_t)bq * INNER_);
    #pragma unroll
    for (int i = threadIdx.x; i < INNER_ / 2; i += 256) {
        float2 f = __half22float2(qsrc[i]);
        qs[i * 2] = f.x; qs[i * 2 + 1] = f.y;
    }
    __syncthreads();

    // ---- K phase: 8-lane cooperative gather ----
    const int g2 = lane >> 3;       // neighbor group 0..3
    const int e  = lane & 7;        // eighth 0..7 (8 dims each)
    float pv[8];
    #pragma unroll
    for (int p = 0; p < 8; p++) {
        const int rj = rows_s[p * 4 + g2];
        const uint4 u = *(const uint4*)(g_kv16
            + (size_t)rj * (2 * INNER_) + h * DH_ + e * 8);
        const float* qp = qs + h * DH_ + e * 8;
        float t = 0.f;
        {
            float2 f;
            f = __half22float2(*(__half2*)&u.x); t = fmaf(qp[0], f.x, t); t = fmaf(qp[1], f.y, t);
            f = __half22float2(*(__half2*)&u.y); t = fmaf(qp[2], f.x, t); t = fmaf(qp[3], f.y, t);
            f = __half22float2(*(__half2*)&u.z); t = fmaf(qp[4], f.x, t); t = fmaf(qp[5], f.y, t);
            f = __half22float2(*(__half2*)&u.w); t = fmaf(qp[6], f.x, t); t = fmaf(qp[7], f.y, t);
        }
        t += __shfl_xor_sync(0xffffffffu, t, 1);
        t += __shfl_xor_sync(0xffffffffu, t, 2);
        t += __shfl_xor_sync(0xffffffffu, t, 4);
        pv[p] = t;                  // all 8 lanes of group g2 hold sim_{4p+g2}
    }
    // redistribute: lane l wants sim_l = pv[l>>2] from lane (l&3)*8
    const int src = (lane & 3) << 3;
    float tt[8];
    #pragma unroll
    for (int p = 0; p < 8; p++) tt[p] = __shfl_sync(0xffffffffu, pv[p], src);
    const int psel = lane >> 2;
    float dot =
        (psel < 4) ? ((psel < 2) ? (psel == 0 ? tt[0] : tt[1])
                                 : (psel == 2 ? tt[2] : tt[3]))
                   : ((psel < 6) ? (psel == 4 ? tt[4] : tt[5])
                                 : (psel == 6 ? tt[6] : tt[7]));

    const float bj  = bias[(size_t)bq * KN_ + lane];
    float sim = dot * 0.125f + bj;

    // ---- softmax (lane j holds sim_j) ----
    float m = sim;
    #pragma unroll
    for (int o = 16; o; o >>= 1) m = fmaxf(m, __shfl_xor_sync(0xffffffffu, m, o));
    float eexp = __expf(sim - m);
    float s = eexp;
    #pragma unroll
    for (int o = 16; o; o >>= 1) s += __shfl_xor_sync(0xffffffffu, s, o);
    const float p = eexp / s;

    ps[h][lane] = p;
    __syncthreads();

    // ---- V phase: batched coalesced loads ----
    float2 acc = make_float2(0.f, 0.f);
    const int off = INNER_ + h * DH_ + lane * 2;
    #pragma unroll
    for (int jb = 0; jb < KN_; jb += 8) {
        float2 v2[8];
        #pragma unroll
        for (int u2 = 0; u2 < 8; u2++) {
            const int rj = rows_s[jb + u2];
            v2[u2] = __half22float2(
                *(const __half2*)(g_kv16 + (size_t)rj * (2 * INNER_) + off));
        }
        #pragma unroll
        for (int u2 = 0; u2 < 8; u2++) {
            const float pj = ps[h][jb + u2];
            acc.x = fmaf(pj, v2[u2].x, acc.x);
            acc.y = fmaf(pj, v2[u2].y, acc.y);
        }
    }
    *(__half2*)(g_at16 + (size_t)bq * INNER_ + h * DH_ + lane * 2) =
        __floats2half2_rn(acc.x, acc.y);
}

// ---------------------------------------------------------------------------
extern "C" void kernel_launch(void* const* d_in, const int* in_sizes, int n_in,
                              void* d_out, int out_size)
{
    const float* x       = (const float*)d_in[0];
    const float* context = (const float*)d_in[1];
    const int*   idx     = (const int*)d_in[2];
    const float* bias    = (const float*)d_in[3];
    const float* Wq      = (const float*)d_in[4];
    const float* Wkv     = (const float*)d_in[5];
    const float* Wo      = (const float*)d_in[6];
    const float* bo      = (const float*)d_in[7];
    float*       out     = (float*)d_out;

    cudaFuncSetAttribute(qkv_gemm,
        cudaFuncAttributeMaxDynamicSharedMemorySize, SMEM_BYTES);
    cudaFuncSetAttribute(out_gemm,
        cudaFuncAttributeMaxDynamicSharedMemorySize, SMEM_BYTES);

    convert_all<<<CVT_BLOCKS, 256>>>(
        (const float4*)x, (const float4*)context,
        (const float4*)Wq, (const float4*)Wkv, (const float4*)Wo);

    qkv_gemm<<<dim3(4, 256), 256, SMEM_BYTES>>>();

    attn_kernel<<<MQ, 256>>>(idx, bias);

    out_gemm<<<dim3(4, MQ / 128), 256, SMEM_BYTES>>>(out, bo);
}